// round 16
// baseline (speedup 1.0000x reference)
#include <cuda_runtime.h>
#include <cuda_bf16.h>
#include <mma.h>
#include <math.h>
#include <stdint.h>

using namespace nvcuda;
typedef __nv_bfloat16 bf16;

// Problem constants
#define NB   2
#define NT   2048
#define ND   512
#define NH   8
#define NHD  64
#define NQKV 1536
#define MAXROWS (NB*NT)        // 4096
#define PADROWS (MAXROWS+128)
#define KSPLIT 4

// ---------------- scratch (device globals; no allocations allowed) ----------
__device__ float d_S     [ (size_t)NB*NH*NT*NT ];     // exp(scores), ld = NT
__device__ float d_AO    [ (size_t)PADROWS*ND ];
__device__ float d_AOp   [ (size_t)KSPLIT*PADROWS*ND ];   // split-K partials
__device__ float d_stage [ (size_t)PADROWS*ND ];
__device__ float d_merged[ (size_t)PADROWS*ND ];
__device__ float d_rinv  [ NB*NH*NT ];                // 1 / sum(exp row)

// bf16 hi/lo planes (persistent activation/weight format)
__device__ __align__(16) bf16 d_Qh[(size_t)PADROWS*NQKV];   // qkv output planes
__device__ __align__(16) bf16 d_Ql[(size_t)PADROWS*NQKV];
__device__ __align__(16) bf16 d_Xh[(size_t)PADROWS*ND];     // dense-GEMM A planes
__device__ __align__(16) bf16 d_Xl[(size_t)PADROWS*ND];
__device__ __align__(16) bf16 d_Wh[(size_t)NQKV*ND];        // weight planes
__device__ __align__(16) bf16 d_Wl[(size_t)NQKV*ND];

__device__ int g_ids1[NT];
__device__ int g_ids2[NT];
__device__ int g_start1[NT+2];
__device__ int g_start2[NT+2];
__device__ int g_m1, g_m2, g_ntok;
__device__ int g_tokmap[NT];
__device__ int g_tokg[NT];
__device__ long long g_off[3];

__device__ __forceinline__ int seqlen(int stage) {
    return stage == 0 ? NT : (stage == 1 ? g_m1 : g_m2);
}

__device__ __forceinline__ void split_bf(float v, bf16& h, bf16& l) {
    h = __float2bfloat16(v);
    l = __float2bfloat16(v - __bfloat162float(h));
}

// ---------------- setup: one block, smem-resident, parallel writes ----------
__global__ __launch_bounds__(256)
void setup_kernel(const float* __restrict__ mw, const float* __restrict__ mb,
                  const float* __restrict__ gw, const float* __restrict__ gb) {
    __shared__ float stagef[ND];
    __shared__ int ids1s[NT];
    __shared__ int ids2s[NT];
    __shared__ float s_c1, s_c2;
    __shared__ int s_m1, s_m2, s_t0;
    int t = threadIdx.x;

    for (int i = t; i < ND; i += 256) stagef[i] = mw[i];
    if (t == 0) s_t0 = NT;
    __syncthreads();
    if (t == 0) {
        double s = 0.0;
        for (int i = 0; i < ND; i++) s += (double)stagef[i];
        s_c1 = (float)s + mb[0];
    }
    __syncthreads();
    for (int i = t; i < ND; i += 256) stagef[i] = gw[i];
    __syncthreads();
    if (t == 0) {
        double s = 0.0;
        for (int i = 0; i < ND; i++) s += (double)stagef[i];
        s_c2 = (float)s + gb[0];

        float c1 = s_c1;
        float cum = 0.f, last = 0.f;
        for (int i = 0; i < NT; i++) { cum += c1; last = cum - floorf(cum); }
        cum = 0.f; float prev = last; int id = 0;
        for (int i = 0; i < NT; i++) {
            cum += c1;
            float fr = cum - floorf(cum);
            if (fr < prev) id++;
            ids1s[i] = id;
            prev = fr;
        }
        s_m1 = id;
    }
    __syncthreads();
    int m1 = s_m1;

    for (int i = t; i < NT; i += 256) {
        int v = ids1s[i];
        g_ids1[i] = v;
        if (i > 0 && v != ids1s[i - 1]) g_start1[v] = i;
    }
    if (t == 0) {
        if (ids1s[0] >= 1) g_start1[1] = 0;
        g_start1[m1 + 1] = NT;
    }

    if (t == 0) {
        float c2 = s_c2;
        float cum = 0.f, last = 0.f;
        for (int i = 0; i < m1; i++) { cum += c2; last = cum - floorf(cum); }
        cum = 0.f; float prev = last; int id = 0;
        for (int i = 0; i < m1; i++) {
            cum += c2;
            float fr = cum - floorf(cum);
            if (fr < prev) id++;
            ids2s[i] = id;
            prev = fr;
        }
        s_m2 = id;
    }
    __syncthreads();
    int m2 = s_m2;

    for (int i = t; i < m1; i += 256) {
        int v = ids2s[i];
        g_ids2[i] = v;
        if (i > 0 && v != ids2s[i - 1]) g_start2[v] = i;
    }
    if (t == 0) {
        if (ids2s[0] >= 1) g_start2[1] = 0;
        g_start2[m2 + 1] = m1;
    }
    __syncthreads();

    for (int i = t; i < NT; i += 256) {
        int i1 = ids1s[i];
        int tg = (i1 >= 1) ? ids2s[i1 - 1] : 0;
        g_tokg[i] = tg;
        if (tg >= 1) atomicMin(&s_t0, i);
    }
    __syncthreads();
    int t0 = s_t0;
    int n = NT - t0;
    for (int i = t; i < n; i += 256) g_tokmap[i] = t0 + i;

    if (t == 0) {
        g_m1 = m1; g_m2 = m2; g_ntok = n;
        long long offcw = (long long)NB * n * ND;
        g_off[0] = offcw;
        g_off[1] = offcw + (long long)NB * NT * NT;
        g_off[2] = g_off[1] + (long long)NB * m1 * m1;
    }
}

// ---------------- fp32 -> bf16 hi/lo split (selector-based pointers) --------
// srcsel: 0 = external arg, 1 = d_AO, 2 = d_merged
// dstsel: 0 = X planes,     1 = W planes
__global__ __launch_bounds__(256)
void k_split(const float* __restrict__ ext, int srcsel, int dstsel, long long n) {
    const float* src = (srcsel == 0) ? ext : (srcsel == 1 ? d_AO : d_merged);
    bf16* dh = (dstsel == 0) ? d_Xh : d_Wh;
    bf16* dl = (dstsel == 0) ? d_Xl : d_Wl;
    for (long long i = ((long long)blockIdx.x * 256 + threadIdx.x) * 4; i < n;
         i += (long long)gridDim.x * 1024) {
        float4 v = *(const float4*)(src + i);
        bf16 h0, l0, h1, l1, h2, l2, h3, l3;
        split_bf(v.x, h0, l0); split_bf(v.y, h1, l1);
        split_bf(v.z, h2, l2); split_bf(v.w, h3, l3);
        *(__nv_bfloat162*)(dh + i)     = __nv_bfloat162(h0, h1);
        *(__nv_bfloat162*)(dh + i + 2) = __nv_bfloat162(h2, h3);
        *(__nv_bfloat162*)(dl + i)     = __nv_bfloat162(l0, l1);
        *(__nv_bfloat162*)(dl + i + 2) = __nv_bfloat162(l2, l3);
    }
}

// ---------------- shared tile geometry --------------------------------------
#define BM 128
#define BN 64
#define BK 32
#define LDSB 40
#define SMEM_BYTES 32768

// MMA inner step (identical across kernels): 12 frag loads, 12 MMAs
#define MMA_STEP(As_hi, As_lo, Bs_hi, Bs_lo)                                        \
    _Pragma("unroll")                                                               \
    for (int kk = 0; kk < BK; kk += 16) {                                           \
        wmma::fragment<wmma::matrix_a, 16, 16, 16, bf16, wmma::row_major> ah[2], al[2]; \
        wmma::fragment<wmma::matrix_b, 16, 16, 16, bf16, wmma::col_major> bh[2], bl[2]; \
        _Pragma("unroll")                                                           \
        for (int i = 0; i < 2; i++) {                                               \
            wmma::load_matrix_sync(ah[i], &As_hi[(wm0 + i * 16) * LDSB + kk], LDSB);\
            wmma::load_matrix_sync(al[i], &As_lo[(wm0 + i * 16) * LDSB + kk], LDSB);\
        }                                                                           \
        _Pragma("unroll")                                                           \
        for (int j = 0; j < 2; j++) {                                               \
            wmma::load_matrix_sync(bh[j], &Bs_hi[(wn0 + j * 16) * LDSB + kk], LDSB);\
            wmma::load_matrix_sync(bl[j], &Bs_lo[(wn0 + j * 16) * LDSB + kk], LDSB);\
        }                                                                           \
        _Pragma("unroll")                                                           \
        for (int i = 0; i < 2; i++)                                                 \
            _Pragma("unroll")                                                       \
            for (int j = 0; j < 2; j++) {                                           \
                wmma::mma_sync(acc[i][j], ah[i], bh[j], acc[i][j]);                 \
                wmma::mma_sync(acc[i][j], al[i], bh[j], acc[i][j]);                 \
                wmma::mma_sync(acc[i][j], ah[i], bl[j], acc[i][j]);                 \
            }                                                                       \
    }

// =============== dense GEMM: X planes @ W planes^T ==========================
// Csel 0: out -> Q planes (+bias, split);  Csel 1: out -> d_stage fp32 (+bias)
__global__ __launch_bounds__(256, 3)
void k_gemm2(const float* __restrict__ bias, int Csel, int N, int stage) {
    int M = NB * seqlen(stage);
    int m0 = blockIdx.y * BM;
    if (m0 >= M) return;
    int n0 = blockIdx.x * BN;
    const int K = ND;

    __shared__ __align__(16) char smem_raw[SMEM_BYTES];
    bf16* As_hi = (bf16*)smem_raw;
    bf16* As_lo = As_hi + BM * LDSB;
    bf16* Bs_hi = As_lo + BM * LDSB;
    bf16* Bs_lo = Bs_hi + BN * LDSB;

    const int tid  = threadIdx.x;
    const int warp = tid >> 5;
    const int wm0 = (warp & 3) * 32;
    const int wn0 = (warp >> 2) * 32;

    wmma::fragment<wmma::accumulator, 16, 16, 16, float> acc[2][2];
    #pragma unroll
    for (int i = 0; i < 2; i++)
        #pragma unroll
        for (int j = 0; j < 2; j++) wmma::fill_fragment(acc[i][j], 0.f);

    for (int k0 = 0; k0 < K; k0 += BK) {
        #pragma unroll
        for (int ii = 0; ii < 2; ii++) {
            int i = tid + ii * 256;
            int r = i >> 2, c8 = (i & 3) * 8;
            int gr = m0 + r, gk = k0 + c8;
            if (gr < M) {
                *(uint4*)&As_hi[r * LDSB + c8] = *(const uint4*)(d_Xh + (size_t)gr * K + gk);
                *(uint4*)&As_lo[r * LDSB + c8] = *(const uint4*)(d_Xl + (size_t)gr * K + gk);
            } else {
                uint4 z = make_uint4(0u, 0u, 0u, 0u);
                *(uint4*)&As_hi[r * LDSB + c8] = z;
                *(uint4*)&As_lo[r * LDSB + c8] = z;
            }
        }
        {
            int r = tid >> 2, c8 = (tid & 3) * 8;
            int gn = n0 + r, gk = k0 + c8;
            *(uint4*)&Bs_hi[r * LDSB + c8] = *(const uint4*)(d_Wh + (size_t)gn * K + gk);
            *(uint4*)&Bs_lo[r * LDSB + c8] = *(const uint4*)(d_Wl + (size_t)gn * K + gk);
        }
        __syncthreads();
        MMA_STEP(As_hi, As_lo, Bs_hi, Bs_lo)
        __syncthreads();
    }

    float* eb = (float*)smem_raw;
    #pragma unroll
    for (int i = 0; i < 2; i++)
        #pragma unroll
        for (int j = 0; j < 2; j++)
            wmma::store_matrix_sync(eb + (wm0 + i * 16) * BN + (wn0 + j * 16),
                                    acc[i][j], BN, wmma::mem_row_major);
    __syncthreads();
    #pragma unroll
    for (int ii = 0; ii < 32; ii++) {
        int idx = tid + ii * 256;
        int r = idx >> 6, c = idx & 63;
        int gr = m0 + r, gc = n0 + c;
        if (gr < M && gc < N) {
            float v = eb[idx] + bias[gc];
            if (Csel == 0) {
                bf16 h, l; split_bf(v, h, l);
                d_Qh[(size_t)gr * NQKV + gc] = h;
                d_Ql[(size_t)gr * NQKV + gc] = l;
            } else {
                d_stage[(size_t)gr * ND + gc] = v;
            }
        }
    }
}

// =============== scores: exp(Q K^T / 8) from Q planes (pure copy loaders) ===
__global__ __launch_bounds__(256, 3)
void k_scores(int stage) {
    int L = seqlen(stage);
    int m0 = blockIdx.y * BM, n0 = blockIdx.x * BN;
    if (m0 >= L || n0 >= L) return;
    int bh = blockIdx.z;
    int b = bh / NH, h = bh % NH;
    size_t qoff = (size_t)b * L * NQKV + h * NHD;   // Q base; K base = qoff + ND
    float* S = d_S + (size_t)bh * NT * NT;
    const int K = NHD;                               // 64

    __shared__ __align__(16) char smem_raw[SMEM_BYTES];
    bf16* As_hi = (bf16*)smem_raw;
    bf16* As_lo = As_hi + BM * LDSB;
    bf16* Bs_hi = As_lo + BM * LDSB;
    bf16* Bs_lo = Bs_hi + BN * LDSB;

    const int tid  = threadIdx.x;
    const int warp = tid >> 5;
    const int wm0 = (warp & 3) * 32;
    const int wn0 = (warp >> 2) * 32;

    wmma::fragment<wmma::accumulator, 16, 16, 16, float> acc[2][2];
    #pragma unroll
    for (int i = 0; i < 2; i++)
        #pragma unroll
        for (int j = 0; j < 2; j++) wmma::fill_fragment(acc[i][j], 0.f);

    for (int k0 = 0; k0 < K; k0 += BK) {
        // A tile (Q rows): 128 x 32, guard rows (K dims always full)
        #pragma unroll
        for (int ii = 0; ii < 2; ii++) {
            int i = tid + ii * 256;
            int r = i >> 2, c8 = (i & 3) * 8;
            int gr = m0 + r, gk = k0 + c8;
            if (gr < L) {
                *(uint4*)&As_hi[r * LDSB + c8] = *(const uint4*)(d_Qh + qoff + (size_t)gr * NQKV + gk);
                *(uint4*)&As_lo[r * LDSB + c8] = *(const uint4*)(d_Ql + qoff + (size_t)gr * NQKV + gk);
            } else {
                uint4 z = make_uint4(0u, 0u, 0u, 0u);
                *(uint4*)&As_hi[r * LDSB + c8] = z;
                *(uint4*)&As_lo[r * LDSB + c8] = z;
            }
        }
        // B tile (K rows): 64 x 32
        {
            int r = tid >> 2, c8 = (tid & 3) * 8;
            int gn = n0 + r, gk = k0 + c8;
            if (gn < L) {
                *(uint4*)&Bs_hi[r * LDSB + c8] = *(const uint4*)(d_Qh + qoff + ND + (size_t)gn * NQKV + gk);
                *(uint4*)&Bs_lo[r * LDSB + c8] = *(const uint4*)(d_Ql + qoff + ND + (size_t)gn * NQKV + gk);
            } else {
                uint4 z = make_uint4(0u, 0u, 0u, 0u);
                *(uint4*)&Bs_hi[r * LDSB + c8] = z;
                *(uint4*)&Bs_lo[r * LDSB + c8] = z;
            }
        }
        __syncthreads();
        MMA_STEP(As_hi, As_lo, Bs_hi, Bs_lo)
        __syncthreads();
    }

    // epilogue: exp(acc/8) stored directly (overhang stays in NT x NT slab)
    #pragma unroll
    for (int i = 0; i < 2; i++)
        #pragma unroll
        for (int j = 0; j < 2; j++) {
            #pragma unroll
            for (int e = 0; e < acc[i][j].num_elements; e++)
                acc[i][j].x[e] = expf(acc[i][j].x[e] * 0.125f);
            wmma::store_matrix_sync(S + (size_t)(m0 + wm0 + i * 16) * NT + (n0 + wn0 + j * 16),
                                    acc[i][j], NT, wmma::mem_row_major);
        }
}

// =============== split-K attn@V: S fp32 (convert) @ V planes (copy) =========
__global__ __launch_bounds__(256, 3)
void k_av(int stage) {
    int L = seqlen(stage);
    int m0 = blockIdx.y * BM;
    if (m0 >= L) return;
    int chunk = blockIdx.x;
    int kchunk = ((L + KSPLIT * BK - 1) / (KSPLIT * BK)) * BK;
    int kstart = chunk * kchunk;
    if (kstart >= L) return;
    int Kc = min(kchunk, L - kstart);
    int bh = blockIdx.z;
    int b = bh / NH, h = bh % NH;
    const float* S = d_S + (size_t)bh * NT * NT + kstart;
    size_t voff = ((size_t)b * L + kstart) * NQKV + 2 * ND + h * NHD;  // V planes base
    float* C = d_AOp + (size_t)chunk * PADROWS * ND + (size_t)b * L * ND + h * NHD;

    __shared__ __align__(16) char smem_raw[SMEM_BYTES];
    bf16* As_hi = (bf16*)smem_raw;
    bf16* As_lo = As_hi + BM * LDSB;
    bf16* Bs_hi = As_lo + BM * LDSB;
    bf16* Bs_lo = Bs_hi + BN * LDSB;

    const int tid  = threadIdx.x;
    const int warp = tid >> 5;
    const int wm0 = (warp & 3) * 32;
    const int wn0 = (warp >> 2) * 32;

    wmma::fragment<wmma::accumulator, 16, 16, 16, float> acc[2][2];
    #pragma unroll
    for (int i = 0; i < 2; i++)
        #pragma unroll
        for (int j = 0; j < 2; j++) wmma::fill_fragment(acc[i][j], 0.f);

    for (int k0 = 0; k0 < Kc; k0 += BK) {
        // A tile: S fp32 128 x 32, convert-in-loader (guard rows vs L, cols vs Kc)
        #pragma unroll
        for (int ii = 0; ii < 4; ii++) {
            int i = tid + ii * 256;
            int r = i >> 3, c4 = (i & 7) * 4;
            int gr = m0 + r, gk = k0 + c4;
            float4 v = make_float4(0.f, 0.f, 0.f, 0.f);
            bool rowok = (gr < L);
            if (rowok && gk + 3 < Kc) {
                v = *(const float4*)(S + (size_t)gr * NT + gk);
            } else if (rowok) {
                if (gk     < Kc) v.x = S[(size_t)gr * NT + gk];
                if (gk + 1 < Kc) v.y = S[(size_t)gr * NT + gk + 1];
                if (gk + 2 < Kc) v.z = S[(size_t)gr * NT + gk + 2];
                if (gk + 3 < Kc) v.w = S[(size_t)gr * NT + gk + 3];
            }
            bf16 hx = __float2bfloat16(v.x);
            bf16 hy = __float2bfloat16(v.y);
            bf16 hz = __float2bfloat16(v.z);
            bf16 hw = __float2bfloat16(v.w);
            *(__nv_bfloat162*)&As_hi[r * LDSB + c4]     = __nv_bfloat162(hx, hy);
            *(__nv_bfloat162*)&As_hi[r * LDSB + c4 + 2] = __nv_bfloat162(hz, hw);
            *(__nv_bfloat162*)&As_lo[r * LDSB + c4] =
                __nv_bfloat162(__float2bfloat16(v.x - __bfloat162float(hx)),
                               __float2bfloat16(v.y - __bfloat162float(hy)));
            *(__nv_bfloat162*)&As_lo[r * LDSB + c4 + 2] =
                __nv_bfloat162(__float2bfloat16(v.z - __bfloat162float(hz)),
                               __float2bfloat16(v.w - __bfloat162float(hw)));
        }
        // B tile: V planes [K, 64] -> transpose to [n][k]; 32 rows x 8 uint4
        {
            int kr = tid >> 3, c8 = (tid & 7) * 8;
            int gk = k0 + kr;
            if (gk < Kc) {
                uint4 vh = *(const uint4*)(d_Qh + voff + (size_t)gk * NQKV + c8);
                uint4 vl = *(const uint4*)(d_Ql + voff + (size_t)gk * NQKV + c8);
                const bf16* ph = (const bf16*)&vh;
                const bf16* pl = (const bf16*)&vl;
                #pragma unroll
                for (int u = 0; u < 8; u++) {
                    Bs_hi[(c8 + u) * LDSB + kr] = ph[u];
                    Bs_lo[(c8 + u) * LDSB + kr] = pl[u];
                }
            } else {
                bf16 z = __float2bfloat16(0.f);
                #pragma unroll
                for (int u = 0; u < 8; u++) {
                    Bs_hi[(c8 + u) * LDSB + kr] = z;
                    Bs_lo[(c8 + u) * LDSB + kr] = z;
                }
            }
        }
        __syncthreads();
        MMA_STEP(As_hi, As_lo, Bs_hi, Bs_lo)
        __syncthreads();
    }

    // epilogue: guarded fp32 store into d_AOp (N = NHD = 64 = BN, cols full)
    float* eb = (float*)smem_raw;
    #pragma unroll
    for (int i = 0; i < 2; i++)
        #pragma unroll
        for (int j = 0; j < 2; j++)
            wmma::store_matrix_sync(eb + (wm0 + i * 16) * BN + (wn0 + j * 16),
                                    acc[i][j], BN, wmma::mem_row_major);
    __syncthreads();
    #pragma unroll
    for (int ii = 0; ii < 32; ii++) {
        int idx = tid + ii * 256;
        int r = idx >> 6, c = idx & 63;
        int gr = m0 + r;
        if (gr < L)
            C[(size_t)gr * ND + c] = eb[idx];
    }
}

__global__ __launch_bounds__(256)
void k_avreduce(int stage) {
    int L = seqlen(stage);
    size_t total = (size_t)NB * L * ND;
    int kchunk = ((L + KSPLIT * BK - 1) / (KSPLIT * BK)) * BK;
    int nv = (L + kchunk - 1) / kchunk;
    for (size_t i = (size_t)blockIdx.x * blockDim.x + threadIdx.x; i < total;
         i += (size_t)gridDim.x * blockDim.x) {
        float s = 0.f;
        for (int c = 0; c < nv; c++) s += d_AOp[(size_t)c * PADROWS * ND + i];
        int d = (int)(i & (ND - 1));
        size_t row = i >> 9;                 // ND = 512
        int q = (int)(row % L);
        int b = (int)(row / L);
        int h = d >> 6;
        d_AO[i] = s * d_rinv[(size_t)(b * NH + h) * NT + q];
    }
}

// ------- rowstat: warp-per-head, smem-staged, 2 barriers --------------------
__global__ __launch_bounds__(256)
void k_rowstat(int stage, float* __restrict__ out) {
    extern __shared__ float sS[];          // NH rows x sLd floats
    __shared__ float rv_s[NH];
    int L = seqlen(stage);
    int q = blockIdx.x;
    if (q >= L) return;
    int b = blockIdx.y;
    int t = threadIdx.x, w = t >> 5, lane = t & 31;
    int sLd = ((L + 3) & ~3) + 4;

    const float* row = d_S + ((size_t)(b * NH + w) * NT + q) * NT;
    float s = 0.f;
    #pragma unroll 4
    for (int k4 = lane * 4; k4 < L; k4 += 128) {
        if (k4 + 3 < L) {
            float4 v = *(const float4*)(row + k4);
            s += (v.x + v.y) + (v.z + v.w);
            *(float4*)&sS[w * sLd + k4] = v;
        } else {
            for (int k = k4; k < L; k++) { float x = row[k]; s += x; sS[w * sLd + k] = x; }
        }
    }
    #pragma unroll
    for (int o = 16; o > 0; o >>= 1) s += __shfl_xor_sync(0xFFFFFFFFu, s, o);
    if (lane == 0) rv_s[w] = 1.f / s;
    __syncthreads();

    float rvl[NH];
    #pragma unroll
    for (int h = 0; h < NH; h++) rvl[h] = rv_s[h];

    float* dst = out + g_off[stage] + ((size_t)b * L + q) * L;
    for (int k = t; k < L; k += 256) {
        float a = 0.f;
        #pragma unroll
        for (int h = 0; h < NH; h++) a += sS[h * sLd + k] * rvl[h];
        dst[k] = 0.125f * a;
    }
    if (t < NH) d_rinv[(size_t)(b * NH + t) * NT + q] = rv_s[t];
}

// ---------------- segment mean merge: d_stage -> d_merged -------------------
__global__ __launch_bounds__(256)
void merge_kernel(int which) {
    int m   = (which == 1) ? g_m1 : g_m2;
    int Tin = (which == 1) ? NT : g_m1;
    const int* start = (which == 1) ? g_start1 : g_start2;
    int j = blockIdx.x + 1;
    if (j > m) return;
    int b = blockIdx.y;
    int s0 = start[j], s1 = start[j + 1];
    float cnt = (float)(s1 - s0);
    const float* in = d_stage + ((size_t)b * Tin) * ND;
    float* outp = d_merged + ((size_t)(b * m + (j - 1))) * ND;
    for (int d = threadIdx.x; d < ND; d += 256) {
        float s = 0.f;
        for (int t = s0; t < s1; t++) s += in[(size_t)t * ND + d];
        outp[d] = s / (cnt + 1e-10f);
    }
}

// ---------------- expand glob_out to selected tokens -> d_out[0..] ----------
__global__ __launch_bounds__(256)
void expand_kernel(float* __restrict__ out) {
    int i = blockIdx.x;
    if (i >= g_ntok) return;
    int b = blockIdx.y;
    int t = g_tokmap[i];
    int gsrc = g_tokg[t] - 1;
    int m2 = g_m2;
    const float* src = d_stage + ((size_t)(b * m2 + gsrc)) * ND;
    float* dst = out + ((size_t)b * g_ntok + i) * ND;
    for (int d = threadIdx.x; d < ND; d += 256) dst[d] = src[d];
}

// ---------------- launch ----------------------------------------------------
#define RS_SMEM (NH * (NT + 8) * 4)   // 65792 B worst case

extern "C" void kernel_launch(void* const* d_in, const int* in_sizes, int n_in,
                              void* d_out, int out_size) {
    (void)in_sizes; (void)n_in; (void)out_size;
    const float* x    = (const float*)d_in[0];
    const float* cWi  = (const float*)d_in[1];
    const float* cbi  = (const float*)d_in[2];
    const float* cWo  = (const float*)d_in[3];
    const float* cbo  = (const float*)d_in[4];
    const float* bWi  = (const float*)d_in[5];
    const float* bbi  = (const float*)d_in[6];
    const float* bWo  = (const float*)d_in[7];
    const float* bbo  = (const float*)d_in[8];
    const float* gWi  = (const float*)d_in[9];
    const float* gbi  = (const float*)d_in[10];
    const float* gWo  = (const float*)d_in[11];
    const float* gbo  = (const float*)d_in[12];
    const float* mw   = (const float*)d_in[13];
    const float* mb   = (const float*)d_in[14];
    const float* gmw  = (const float*)d_in[15];
    const float* gmb  = (const float*)d_in[16];
    float* out = (float*)d_out;

    cudaFuncSetAttribute(k_rowstat, cudaFuncAttributeMaxDynamicSharedMemorySize, RS_SMEM);

    setup_kernel<<<1, 256>>>(mw, mb, gmw, gmb);

    // x -> X planes (stage 0 activations)
    k_split<<<512, 256>>>(x, 0, 0, (long long)MAXROWS * ND);

    const dim3 gQKV(NQKV / BN, MAXROWS / BM);        // (24, 32)
    const dim3 gOUT(ND / BN, MAXROWS / BM);          // (8, 32)
    const dim3 gSC(NT / BN, NT / BM, NB * NH);       // (32, 16, 16)
    const dim3 gAV(KSPLIT, NT / BM, NB * NH);        // (4, 16, 16)
    const dim3 gRS(NT, NB);

    for (int stage = 0; stage < 3; stage++) {
        const float* Wi = stage == 0 ? cWi : (stage == 1 ? bWi : gWi);
        const float* bi = stage == 0 ? cbi : (stage == 1 ? bbi : gbi);
        const float* Wo = stage == 0 ? cWo : (stage == 1 ? bWo : gWo);
        const float* bo = stage == 0 ? cbo : (stage == 1 ? bbo : gbo);

        k_split<<<256, 256>>>(Wi, 0, 1, (long long)NQKV * ND);
        k_gemm2<<<gQKV, 256>>>(bi, 0, NQKV, stage);
        k_scores<<<gSC, 256>>>(stage);
        k_rowstat<<<gRS, 256, RS_SMEM>>>(stage, out);
        k_av<<<gAV, 256>>>(stage);
        k_avreduce<<<2048, 256>>>(stage);
        k_split<<<512, 256>>>(nullptr, 1, 0, (long long)MAXROWS * ND);   // d_AO -> X planes
        k_split<<<256, 256>>>(Wo, 0, 1, (long long)ND * ND);
        k_gemm2<<<gOUT, 256>>>(bo, 1, ND, stage);

        if (stage == 0) {
            merge_kernel<<<dim3(NT, NB), 256>>>(1);
            k_split<<<512, 256>>>(nullptr, 2, 0, (long long)MAXROWS * ND);   // d_merged -> X planes
        }
        if (stage == 1) {
            merge_kernel<<<dim3(NT, NB), 256>>>(2);
            k_split<<<512, 256>>>(nullptr, 2, 0, (long long)MAXROWS * ND);
        }
    }

    expand_kernel<<<dim3(NT, NB), 256>>>(out);
}

// round 17
// speedup vs baseline: 1.1277x; 1.1277x over previous
#include <cuda_runtime.h>
#include <cuda_bf16.h>
#include <cuda_fp16.h>
#include <mma.h>
#include <math.h>
#include <stdint.h>

using namespace nvcuda;
typedef __nv_bfloat16 bf16;

// Problem constants
#define NB   2
#define NT   2048
#define ND   512
#define NH   8
#define NHD  64
#define NQKV 1536
#define MAXROWS (NB*NT)        // 4096
#define PADROWS (MAXROWS+128)
#define KSPLIT 4

// ---------------- scratch (device globals; no allocations allowed) ----------
__device__ __align__(16) __half d_S[(size_t)NB*NH*NT*NT];   // exp(scores), fp16, ld = NT
__device__ float d_AO    [ (size_t)PADROWS*ND ];
__device__ float d_AOp   [ (size_t)KSPLIT*PADROWS*ND ];     // split-K partials
__device__ float d_stage [ (size_t)PADROWS*ND ];
__device__ float d_merged[ (size_t)PADROWS*ND ];
__device__ float d_rinv  [ NB*NH*NT ];                      // 1 / sum(exp row)

// bf16 hi/lo planes (persistent activation/weight format)
__device__ __align__(16) bf16 d_Qh[(size_t)PADROWS*NQKV];   // qkv output planes
__device__ __align__(16) bf16 d_Ql[(size_t)PADROWS*NQKV];
__device__ __align__(16) bf16 d_Xh[(size_t)PADROWS*ND];     // dense-GEMM A planes
__device__ __align__(16) bf16 d_Xl[(size_t)PADROWS*ND];
__device__ __align__(16) bf16 d_Wh[(size_t)NQKV*ND];        // weight planes
__device__ __align__(16) bf16 d_Wl[(size_t)NQKV*ND];

__device__ int g_ids1[NT];
__device__ int g_ids2[NT];
__device__ int g_start1[NT+2];
__device__ int g_start2[NT+2];
__device__ int g_m1, g_m2, g_ntok;
__device__ int g_tokmap[NT];
__device__ int g_tokg[NT];
__device__ long long g_off[3];

__device__ __forceinline__ int seqlen(int stage) {
    return stage == 0 ? NT : (stage == 1 ? g_m1 : g_m2);
}

__device__ __forceinline__ void split_bf(float v, bf16& h, bf16& l) {
    h = __float2bfloat16(v);
    l = __float2bfloat16(v - __bfloat162float(h));
}

// ---------------- setup: one block, smem-resident, parallel writes ----------
__global__ __launch_bounds__(256)
void setup_kernel(const float* __restrict__ mw, const float* __restrict__ mb,
                  const float* __restrict__ gw, const float* __restrict__ gb) {
    __shared__ float stagef[ND];
    __shared__ int ids1s[NT];
    __shared__ int ids2s[NT];
    __shared__ float s_c1, s_c2;
    __shared__ int s_m1, s_m2, s_t0;
    int t = threadIdx.x;

    for (int i = t; i < ND; i += 256) stagef[i] = mw[i];
    if (t == 0) s_t0 = NT;
    __syncthreads();
    if (t == 0) {
        double s = 0.0;
        for (int i = 0; i < ND; i++) s += (double)stagef[i];
        s_c1 = (float)s + mb[0];
    }
    __syncthreads();
    for (int i = t; i < ND; i += 256) stagef[i] = gw[i];
    __syncthreads();
    if (t == 0) {
        double s = 0.0;
        for (int i = 0; i < ND; i++) s += (double)stagef[i];
        s_c2 = (float)s + gb[0];

        float c1 = s_c1;
        float cum = 0.f, last = 0.f;
        for (int i = 0; i < NT; i++) { cum += c1; last = cum - floorf(cum); }
        cum = 0.f; float prev = last; int id = 0;
        for (int i = 0; i < NT; i++) {
            cum += c1;
            float fr = cum - floorf(cum);
            if (fr < prev) id++;
            ids1s[i] = id;
            prev = fr;
        }
        s_m1 = id;
    }
    __syncthreads();
    int m1 = s_m1;

    for (int i = t; i < NT; i += 256) {
        int v = ids1s[i];
        g_ids1[i] = v;
        if (i > 0 && v != ids1s[i - 1]) g_start1[v] = i;
    }
    if (t == 0) {
        if (ids1s[0] >= 1) g_start1[1] = 0;
        g_start1[m1 + 1] = NT;
    }

    if (t == 0) {
        float c2 = s_c2;
        float cum = 0.f, last = 0.f;
        for (int i = 0; i < m1; i++) { cum += c2; last = cum - floorf(cum); }
        cum = 0.f; float prev = last; int id = 0;
        for (int i = 0; i < m1; i++) {
            cum += c2;
            float fr = cum - floorf(cum);
            if (fr < prev) id++;
            ids2s[i] = id;
            prev = fr;
        }
        s_m2 = id;
    }
    __syncthreads();
    int m2 = s_m2;

    for (int i = t; i < m1; i += 256) {
        int v = ids2s[i];
        g_ids2[i] = v;
        if (i > 0 && v != ids2s[i - 1]) g_start2[v] = i;
    }
    if (t == 0) {
        if (ids2s[0] >= 1) g_start2[1] = 0;
        g_start2[m2 + 1] = m1;
    }
    __syncthreads();

    for (int i = t; i < NT; i += 256) {
        int i1 = ids1s[i];
        int tg = (i1 >= 1) ? ids2s[i1 - 1] : 0;
        g_tokg[i] = tg;
        if (tg >= 1) atomicMin(&s_t0, i);
    }
    __syncthreads();
    int t0 = s_t0;
    int n = NT - t0;
    for (int i = t; i < n; i += 256) g_tokmap[i] = t0 + i;

    if (t == 0) {
        g_m1 = m1; g_m2 = m2; g_ntok = n;
        long long offcw = (long long)NB * n * ND;
        g_off[0] = offcw;
        g_off[1] = offcw + (long long)NB * NT * NT;
        g_off[2] = g_off[1] + (long long)NB * m1 * m1;
    }
}

// ---------------- fp32 -> bf16 hi/lo split (selector-based pointers) --------
// srcsel: 0 = external arg, 1 = d_AO, 2 = d_merged
// dstsel: 0 = X planes,     1 = W planes
__global__ __launch_bounds__(256)
void k_split(const float* __restrict__ ext, int srcsel, int dstsel, long long n) {
    const float* src = (srcsel == 0) ? ext : (srcsel == 1 ? d_AO : d_merged);
    bf16* dh = (dstsel == 0) ? d_Xh : d_Wh;
    bf16* dl = (dstsel == 0) ? d_Xl : d_Wl;
    for (long long i = ((long long)blockIdx.x * 256 + threadIdx.x) * 4; i < n;
         i += (long long)gridDim.x * 1024) {
        float4 v = *(const float4*)(src + i);
        bf16 h0, l0, h1, l1, h2, l2, h3, l3;
        split_bf(v.x, h0, l0); split_bf(v.y, h1, l1);
        split_bf(v.z, h2, l2); split_bf(v.w, h3, l3);
        *(__nv_bfloat162*)(dh + i)     = __nv_bfloat162(h0, h1);
        *(__nv_bfloat162*)(dh + i + 2) = __nv_bfloat162(h2, h3);
        *(__nv_bfloat162*)(dl + i)     = __nv_bfloat162(l0, l1);
        *(__nv_bfloat162*)(dl + i + 2) = __nv_bfloat162(l2, l3);
    }
}

// ---------------- shared tile geometry --------------------------------------
#define BM 128
#define BN 64
#define BK 32
#define LDSB 40
#define SMEM_BYTES 32768

// bf16 3-term MMA inner step: 12 frag loads, 12 MMAs
#define MMA_STEP(As_hi, As_lo, Bs_hi, Bs_lo)                                        \
    _Pragma("unroll")                                                               \
    for (int kk = 0; kk < BK; kk += 16) {                                           \
        wmma::fragment<wmma::matrix_a, 16, 16, 16, bf16, wmma::row_major> ah[2], al[2]; \
        wmma::fragment<wmma::matrix_b, 16, 16, 16, bf16, wmma::col_major> bh[2], bl[2]; \
        _Pragma("unroll")                                                           \
        for (int i = 0; i < 2; i++) {                                               \
            wmma::load_matrix_sync(ah[i], &As_hi[(wm0 + i * 16) * LDSB + kk], LDSB);\
            wmma::load_matrix_sync(al[i], &As_lo[(wm0 + i * 16) * LDSB + kk], LDSB);\
        }                                                                           \
        _Pragma("unroll")                                                           \
        for (int j = 0; j < 2; j++) {                                               \
            wmma::load_matrix_sync(bh[j], &Bs_hi[(wn0 + j * 16) * LDSB + kk], LDSB);\
            wmma::load_matrix_sync(bl[j], &Bs_lo[(wn0 + j * 16) * LDSB + kk], LDSB);\
        }                                                                           \
        _Pragma("unroll")                                                           \
        for (int i = 0; i < 2; i++)                                                 \
            _Pragma("unroll")                                                       \
            for (int j = 0; j < 2; j++) {                                           \
                wmma::mma_sync(acc[i][j], ah[i], bh[j], acc[i][j]);                 \
                wmma::mma_sync(acc[i][j], al[i], bh[j], acc[i][j]);                 \
                wmma::mma_sync(acc[i][j], ah[i], bl[j], acc[i][j]);                 \
            }                                                                       \
    }

// =============== dense GEMM: X planes @ W planes^T ==========================
// Csel 0: out -> Q planes (+bias, split);  Csel 1: out -> d_stage fp32 (+bias)
__global__ __launch_bounds__(256, 3)
void k_gemm2(const float* __restrict__ bias, int Csel, int N, int stage) {
    int M = NB * seqlen(stage);
    int m0 = blockIdx.y * BM;
    if (m0 >= M) return;
    int n0 = blockIdx.x * BN;
    const int K = ND;

    __shared__ __align__(16) char smem_raw[SMEM_BYTES];
    bf16* As_hi = (bf16*)smem_raw;
    bf16* As_lo = As_hi + BM * LDSB;
    bf16* Bs_hi = As_lo + BM * LDSB;
    bf16* Bs_lo = Bs_hi + BN * LDSB;

    const int tid  = threadIdx.x;
    const int warp = tid >> 5;
    const int wm0 = (warp & 3) * 32;
    const int wn0 = (warp >> 2) * 32;

    wmma::fragment<wmma::accumulator, 16, 16, 16, float> acc[2][2];
    #pragma unroll
    for (int i = 0; i < 2; i++)
        #pragma unroll
        for (int j = 0; j < 2; j++) wmma::fill_fragment(acc[i][j], 0.f);

    for (int k0 = 0; k0 < K; k0 += BK) {
        #pragma unroll
        for (int ii = 0; ii < 2; ii++) {
            int i = tid + ii * 256;
            int r = i >> 2, c8 = (i & 3) * 8;
            int gr = m0 + r, gk = k0 + c8;
            if (gr < M) {
                *(uint4*)&As_hi[r * LDSB + c8] = *(const uint4*)(d_Xh + (size_t)gr * K + gk);
                *(uint4*)&As_lo[r * LDSB + c8] = *(const uint4*)(d_Xl + (size_t)gr * K + gk);
            } else {
                uint4 z = make_uint4(0u, 0u, 0u, 0u);
                *(uint4*)&As_hi[r * LDSB + c8] = z;
                *(uint4*)&As_lo[r * LDSB + c8] = z;
            }
        }
        {
            int r = tid >> 2, c8 = (tid & 3) * 8;
            int gn = n0 + r, gk = k0 + c8;
            *(uint4*)&Bs_hi[r * LDSB + c8] = *(const uint4*)(d_Wh + (size_t)gn * K + gk);
            *(uint4*)&Bs_lo[r * LDSB + c8] = *(const uint4*)(d_Wl + (size_t)gn * K + gk);
        }
        __syncthreads();
        MMA_STEP(As_hi, As_lo, Bs_hi, Bs_lo)
        __syncthreads();
    }

    float* eb = (float*)smem_raw;
    #pragma unroll
    for (int i = 0; i < 2; i++)
        #pragma unroll
        for (int j = 0; j < 2; j++)
            wmma::store_matrix_sync(eb + (wm0 + i * 16) * BN + (wn0 + j * 16),
                                    acc[i][j], BN, wmma::mem_row_major);
    __syncthreads();
    #pragma unroll
    for (int ii = 0; ii < 32; ii++) {
        int idx = tid + ii * 256;
        int r = idx >> 6, c = idx & 63;
        int gr = m0 + r, gc = n0 + c;
        if (gr < M && gc < N) {
            float v = eb[idx] + bias[gc];
            if (Csel == 0) {
                bf16 h, l; split_bf(v, h, l);
                d_Qh[(size_t)gr * NQKV + gc] = h;
                d_Ql[(size_t)gr * NQKV + gc] = l;
            } else {
                d_stage[(size_t)gr * ND + gc] = v;
            }
        }
    }
}

// =============== scores: exp(Q K^T / 8) -> fp16 S (copy loaders) ============
__global__ __launch_bounds__(256, 3)
void k_scores(int stage) {
    int L = seqlen(stage);
    int m0 = blockIdx.y * BM, n0 = blockIdx.x * BN;
    if (m0 >= L || n0 >= L) return;
    int bh = blockIdx.z;
    int b = bh / NH, h = bh % NH;
    size_t qoff = (size_t)b * L * NQKV + h * NHD;   // Q base; K base = qoff + ND
    __half* S = d_S + (size_t)bh * NT * NT;
    const int K = NHD;                               // 64

    __shared__ __align__(16) char smem_raw[SMEM_BYTES];
    bf16* As_hi = (bf16*)smem_raw;
    bf16* As_lo = As_hi + BM * LDSB;
    bf16* Bs_hi = As_lo + BM * LDSB;
    bf16* Bs_lo = Bs_hi + BN * LDSB;

    const int tid  = threadIdx.x;
    const int warp = tid >> 5;
    const int wm0 = (warp & 3) * 32;
    const int wn0 = (warp >> 2) * 32;

    wmma::fragment<wmma::accumulator, 16, 16, 16, float> acc[2][2];
    #pragma unroll
    for (int i = 0; i < 2; i++)
        #pragma unroll
        for (int j = 0; j < 2; j++) wmma::fill_fragment(acc[i][j], 0.f);

    for (int k0 = 0; k0 < K; k0 += BK) {
        #pragma unroll
        for (int ii = 0; ii < 2; ii++) {
            int i = tid + ii * 256;
            int r = i >> 2, c8 = (i & 3) * 8;
            int gr = m0 + r, gk = k0 + c8;
            if (gr < L) {
                *(uint4*)&As_hi[r * LDSB + c8] = *(const uint4*)(d_Qh + qoff + (size_t)gr * NQKV + gk);
                *(uint4*)&As_lo[r * LDSB + c8] = *(const uint4*)(d_Ql + qoff + (size_t)gr * NQKV + gk);
            } else {
                uint4 z = make_uint4(0u, 0u, 0u, 0u);
                *(uint4*)&As_hi[r * LDSB + c8] = z;
                *(uint4*)&As_lo[r * LDSB + c8] = z;
            }
        }
        {
            int r = tid >> 2, c8 = (tid & 3) * 8;
            int gn = n0 + r, gk = k0 + c8;
            if (gn < L) {
                *(uint4*)&Bs_hi[r * LDSB + c8] = *(const uint4*)(d_Qh + qoff + ND + (size_t)gn * NQKV + gk);
                *(uint4*)&Bs_lo[r * LDSB + c8] = *(const uint4*)(d_Ql + qoff + ND + (size_t)gn * NQKV + gk);
            } else {
                uint4 z = make_uint4(0u, 0u, 0u, 0u);
                *(uint4*)&Bs_hi[r * LDSB + c8] = z;
                *(uint4*)&Bs_lo[r * LDSB + c8] = z;
            }
        }
        __syncthreads();
        MMA_STEP(As_hi, As_lo, Bs_hi, Bs_lo)
        __syncthreads();
    }

    // epilogue: stage fp32 to smem, then exp + fp16 pair-store
    float* eb = (float*)smem_raw;
    #pragma unroll
    for (int i = 0; i < 2; i++)
        #pragma unroll
        for (int j = 0; j < 2; j++)
            wmma::store_matrix_sync(eb + (wm0 + i * 16) * BN + (wn0 + j * 16),
                                    acc[i][j], BN, wmma::mem_row_major);
    __syncthreads();
    #pragma unroll
    for (int ii = 0; ii < 16; ii++) {
        int p = tid + ii * 256;           // pair index over 128x64 tile
        int r = p >> 5, c2 = (p & 31) * 2;
        float v0 = expf(eb[r * BN + c2]     * 0.125f);
        float v1 = expf(eb[r * BN + c2 + 1] * 0.125f);
        *(__half2*)&S[(size_t)(m0 + r) * NT + n0 + c2] = __floats2half2_rn(v0, v1);
    }
}

// =============== split-K attn@V: fp16 S (copy) @ V fp16 hi/lo (2-term) ======
__global__ __launch_bounds__(256, 3)
void k_av(int stage) {
    int L = seqlen(stage);
    int m0 = blockIdx.y * BM;
    if (m0 >= L) return;
    int chunk = blockIdx.x;
    int kchunk = ((L + KSPLIT * BK - 1) / (KSPLIT * BK)) * BK;
    int kstart = chunk * kchunk;
    if (kstart >= L) return;
    int Kc = min(kchunk, L - kstart);
    int bh = blockIdx.z;
    int b = bh / NH, h = bh % NH;
    const __half* S = d_S + (size_t)bh * NT * NT + kstart;
    size_t voff = ((size_t)b * L + kstart) * NQKV + 2 * ND + h * NHD;  // V planes base
    float* C = d_AOp + (size_t)chunk * PADROWS * ND + (size_t)b * L * ND + h * NHD;

    __shared__ __align__(16) char smem_raw[SMEM_BYTES];
    __half* As    = (__half*)smem_raw;              // BM x LDSB
    __half* Bs_hi = As + BM * LDSB;                 // BN x LDSB
    __half* Bs_lo = Bs_hi + BN * LDSB;

    const int tid  = threadIdx.x;
    const int warp = tid >> 5;
    const int wm0 = (warp & 3) * 32;
    const int wn0 = (warp >> 2) * 32;

    wmma::fragment<wmma::accumulator, 16, 16, 16, float> acc[2][2];
    #pragma unroll
    for (int i = 0; i < 2; i++)
        #pragma unroll
        for (int j = 0; j < 2; j++) wmma::fill_fragment(acc[i][j], 0.f);

    for (int k0 = 0; k0 < Kc; k0 += BK) {
        // A tile: S fp16, pure copy; 128x32 halves = 512 uint4 -> 2 iters
        #pragma unroll
        for (int ii = 0; ii < 2; ii++) {
            int i = tid + ii * 256;
            int r = i >> 2, c8 = (i & 3) * 8;
            int gr = m0 + r, gk = k0 + c8;
            if (gr < L && gk + 7 < Kc) {
                *(uint4*)&As[r * LDSB + c8] = *(const uint4*)(S + (size_t)gr * NT + gk);
            } else {
                #pragma unroll
                for (int u = 0; u < 8; u++)
                    As[r * LDSB + c8 + u] = (gr < L && gk + u < Kc)
                        ? S[(size_t)gr * NT + gk + u] : __float2half(0.f);
            }
        }
        // B tile: V bf16 planes [K, 64] -> fp16 hi/lo transposed [n][k]
        {
            int kr = tid >> 3, c8 = (tid & 7) * 8;
            int gk = k0 + kr;
            if (gk < Kc) {
                uint4 vh = *(const uint4*)(d_Qh + voff + (size_t)gk * NQKV + c8);
                uint4 vl = *(const uint4*)(d_Ql + voff + (size_t)gk * NQKV + c8);
                const bf16* ph = (const bf16*)&vh;
                const bf16* pl = (const bf16*)&vl;
                #pragma unroll
                for (int u = 0; u < 8; u++) {
                    Bs_hi[(c8 + u) * LDSB + kr] = __float2half(__bfloat162float(ph[u]));
                    Bs_lo[(c8 + u) * LDSB + kr] = __float2half(__bfloat162float(pl[u]));
                }
            } else {
                __half z = __float2half(0.f);
                #pragma unroll
                for (int u = 0; u < 8; u++) {
                    Bs_hi[(c8 + u) * LDSB + kr] = z;
                    Bs_lo[(c8 + u) * LDSB + kr] = z;
                }
            }
        }
        __syncthreads();

        #pragma unroll
        for (int kk = 0; kk < BK; kk += 16) {
            wmma::fragment<wmma::matrix_a, 16, 16, 16, __half, wmma::row_major> a_[2];
            wmma::fragment<wmma::matrix_b, 16, 16, 16, __half, wmma::col_major> bh_[2], bl_[2];
            #pragma unroll
            for (int i = 0; i < 2; i++)
                wmma::load_matrix_sync(a_[i], &As[(wm0 + i * 16) * LDSB + kk], LDSB);
            #pragma unroll
            for (int j = 0; j < 2; j++) {
                wmma::load_matrix_sync(bh_[j], &Bs_hi[(wn0 + j * 16) * LDSB + kk], LDSB);
                wmma::load_matrix_sync(bl_[j], &Bs_lo[(wn0 + j * 16) * LDSB + kk], LDSB);
            }
            #pragma unroll
            for (int i = 0; i < 2; i++)
                #pragma unroll
                for (int j = 0; j < 2; j++) {
                    wmma::mma_sync(acc[i][j], a_[i], bh_[j], acc[i][j]);
                    wmma::mma_sync(acc[i][j], a_[i], bl_[j], acc[i][j]);
                }
        }
        __syncthreads();
    }

    // epilogue: guarded fp32 store into d_AOp (N = NHD = 64 = BN)
    float* eb = (float*)smem_raw;
    #pragma unroll
    for (int i = 0; i < 2; i++)
        #pragma unroll
        for (int j = 0; j < 2; j++)
            wmma::store_matrix_sync(eb + (wm0 + i * 16) * BN + (wn0 + j * 16),
                                    acc[i][j], BN, wmma::mem_row_major);
    __syncthreads();
    #pragma unroll
    for (int ii = 0; ii < 32; ii++) {
        int idx = tid + ii * 256;
        int r = idx >> 6, c = idx & 63;
        int gr = m0 + r;
        if (gr < L)
            C[(size_t)gr * ND + c] = eb[idx];
    }
}

__global__ __launch_bounds__(256)
void k_avreduce(int stage) {
    int L = seqlen(stage);
    size_t total = (size_t)NB * L * ND;
    int kchunk = ((L + KSPLIT * BK - 1) / (KSPLIT * BK)) * BK;
    int nv = (L + kchunk - 1) / kchunk;
    for (size_t i = (size_t)blockIdx.x * blockDim.x + threadIdx.x; i < total;
         i += (size_t)gridDim.x * blockDim.x) {
        float s = 0.f;
        for (int c = 0; c < nv; c++) s += d_AOp[(size_t)c * PADROWS * ND + i];
        int d = (int)(i & (ND - 1));
        size_t row = i >> 9;                 // ND = 512
        int q = (int)(row % L);
        int b = (int)(row / L);
        int h = d >> 6;
        d_AO[i] = s * d_rinv[(size_t)(b * NH + h) * NT + q];
    }
}

// ------- rowstat: warp-per-head, fp16 S read, smem-staged -------------------
__global__ __launch_bounds__(256)
void k_rowstat(int stage, float* __restrict__ out) {
    extern __shared__ float sS[];          // NH rows x sLd floats
    __shared__ float rv_s[NH];
    int L = seqlen(stage);
    int q = blockIdx.x;
    if (q >= L) return;
    int b = blockIdx.y;
    int t = threadIdx.x, w = t >> 5, lane = t & 31;
    int sLd = ((L + 7) & ~7) + 8;

    const __half* row = d_S + ((size_t)(b * NH + w) * NT + q) * NT;
    float s = 0.f;
    for (int k8 = lane * 8; k8 < L; k8 += 256) {
        if (k8 + 7 < L) {
            uint4 v = *(const uint4*)(row + k8);
            const __half* ph = (const __half*)&v;
            #pragma unroll
            for (int u = 0; u < 8; u++) {
                float x = __half2float(ph[u]);
                sS[w * sLd + k8 + u] = x;
                s += x;
            }
        } else {
            for (int k = k8; k < L; k++) {
                float x = __half2float(row[k]);
                sS[w * sLd + k] = x;
                s += x;
            }
        }
    }
    #pragma unroll
    for (int o = 16; o > 0; o >>= 1) s += __shfl_xor_sync(0xFFFFFFFFu, s, o);
    if (lane == 0) rv_s[w] = 1.f / s;
    __syncthreads();

    float rvl[NH];
    #pragma unroll
    for (int h = 0; h < NH; h++) rvl[h] = rv_s[h];

    float* dst = out + g_off[stage] + ((size_t)b * L + q) * L;
    for (int k = t; k < L; k += 256) {
        float a = 0.f;
        #pragma unroll
        for (int h = 0; h < NH; h++) a += sS[h * sLd + k] * rvl[h];
        dst[k] = 0.125f * a;
    }
    if (t < NH) d_rinv[(size_t)(b * NH + t) * NT + q] = rv_s[t];
}

// ---------------- segment mean merge: d_stage -> d_merged -------------------
__global__ __launch_bounds__(256)
void merge_kernel(int which) {
    int m   = (which == 1) ? g_m1 : g_m2;
    int Tin = (which == 1) ? NT : g_m1;
    const int* start = (which == 1) ? g_start1 : g_start2;
    int j = blockIdx.x + 1;
    if (j > m) return;
    int b = blockIdx.y;
    int s0 = start[j], s1 = start[j + 1];
    float cnt = (float)(s1 - s0);
    const float* in = d_stage + ((size_t)b * Tin) * ND;
    float* outp = d_merged + ((size_t)(b * m + (j - 1))) * ND;
    for (int d = threadIdx.x; d < ND; d += 256) {
        float s = 0.f;
        for (int t = s0; t < s1; t++) s += in[(size_t)t * ND + d];
        outp[d] = s / (cnt + 1e-10f);
    }
}

// ---------------- expand glob_out to selected tokens -> d_out[0..] ----------
__global__ __launch_bounds__(256)
void expand_kernel(float* __restrict__ out) {
    int i = blockIdx.x;
    if (i >= g_ntok) return;
    int b = blockIdx.y;
    int t = g_tokmap[i];
    int gsrc = g_tokg[t] - 1;
    int m2 = g_m2;
    const float* src = d_stage + ((size_t)(b * m2 + gsrc)) * ND;
    float* dst = out + ((size_t)b * g_ntok + i) * ND;
    for (int d = threadIdx.x; d < ND; d += 256) dst[d] = src[d];
}

// ---------------- launch ----------------------------------------------------
#define RS_SMEM (NH * (NT + 16) * 4)

extern "C" void kernel_launch(void* const* d_in, const int* in_sizes, int n_in,
                              void* d_out, int out_size) {
    (void)in_sizes; (void)n_in; (void)out_size;
    const float* x    = (const float*)d_in[0];
    const float* cWi  = (const float*)d_in[1];
    const float* cbi  = (const float*)d_in[2];
    const float* cWo  = (const float*)d_in[3];
    const float* cbo  = (const float*)d_in[4];
    const float* bWi  = (const float*)d_in[5];
    const float* bbi  = (const float*)d_in[6];
    const float* bWo  = (const float*)d_in[7];
    const float* bbo  = (const float*)d_in[8];
    const float* gWi  = (const float*)d_in[9];
    const float* gbi  = (const float*)d_in[10];
    const float* gWo  = (const float*)d_in[11];
    const float* gbo  = (const float*)d_in[12];
    const float* mw   = (const float*)d_in[13];
    const float* mb   = (const float*)d_in[14];
    const float* gmw  = (const float*)d_in[15];
    const float* gmb  = (const float*)d_in[16];
    float* out = (float*)d_out;

    cudaFuncSetAttribute(k_rowstat, cudaFuncAttributeMaxDynamicSharedMemorySize, RS_SMEM);

    setup_kernel<<<1, 256>>>(mw, mb, gmw, gmb);

    // x -> X planes (stage 0 activations)
    k_split<<<512, 256>>>(x, 0, 0, (long long)MAXROWS * ND);

    const dim3 gQKV(NQKV / BN, MAXROWS / BM);        // (24, 32)
    const dim3 gOUT(ND / BN, MAXROWS / BM);          // (8, 32)
    const dim3 gSC(NT / BN, NT / BM, NB * NH);       // (32, 16, 16)
    const dim3 gAV(KSPLIT, NT / BM, NB * NH);        // (4, 16, 16)
    const dim3 gRS(NT, NB);

    for (int stage = 0; stage < 3; stage++) {
        const float* Wi = stage == 0 ? cWi : (stage == 1 ? bWi : gWi);
        const float* bi = stage == 0 ? cbi : (stage == 1 ? bbi : gbi);
        const float* Wo = stage == 0 ? cWo : (stage == 1 ? bWo : gWo);
        const float* bo = stage == 0 ? cbo : (stage == 1 ? bbo : gbo);

        k_split<<<256, 256>>>(Wi, 0, 1, (long long)NQKV * ND);
        k_gemm2<<<gQKV, 256>>>(bi, 0, NQKV, stage);
        k_scores<<<gSC, 256>>>(stage);
        k_rowstat<<<gRS, 256, RS_SMEM>>>(stage, out);
        k_av<<<gAV, 256>>>(stage);
        k_avreduce<<<2048, 256>>>(stage);
        k_split<<<512, 256>>>(nullptr, 1, 0, (long long)MAXROWS * ND);   // d_AO -> X planes
        k_split<<<256, 256>>>(Wo, 0, 1, (long long)ND * ND);
        k_gemm2<<<gOUT, 256>>>(bo, 1, ND, stage);

        if (stage == 0) {
            merge_kernel<<<dim3(NT, NB), 256>>>(1);
            k_split<<<512, 256>>>(nullptr, 2, 0, (long long)MAXROWS * ND);   // d_merged -> X planes
        }
        if (stage == 1) {
            merge_kernel<<<dim3(NT, NB), 256>>>(2);
            k_split<<<512, 256>>>(nullptr, 2, 0, (long long)MAXROWS * ND);
        }
    }

    expand_kernel<<<dim3(NT, NB), 256>>>(out);
}